// round 14
// baseline (speedup 1.0000x reference)
#include <cuda_runtime.h>
#include <math.h>

#define BB 2
#define CC 256
#define NHEADS 8
#define HD 32
#define NN 1600
#define C3 768
#define BH 16
#define SCALE 0.17677669529663687f  // 1/sqrt(32)
#define QPAD 73

// ---------------- scratch ----------------
__device__ float g_qkv0[BB * C3 * NN];
__device__ float g_qkv1[BB * C3 * NN];
__device__ float g_attn[(size_t)BH * NN * NN];     // e = exp(logit), all > 0
__device__ float g_S[BH * NN];
__device__ float g_T[BH * NN];
__device__ int   g_keep[BH];
__device__ float g_attout[BB * NN * CC];

// ---------------- helpers ----------------
__device__ __forceinline__ float key2f(unsigned int k) {
    return __uint_as_float(k ^ 0x80000000u);
}

__device__ __forceinline__ unsigned int f2tf32(float x) {
    unsigned int r;
    asm("cvt.rna.tf32.f32 %0, %1;" : "=r"(r) : "f"(x));
    return r;
}

// FMA-pipe exp: 2^(x*log2e) with magic-number range reduction + deg-5 Taylor.
// rel err ~2e-6 for |x| < 80. Avoids MUFU entirely.
__device__ __forceinline__ float fexp(float x) {
    float t = x * 1.4426950408889634f;
    float z = t + 12582912.f;                      // round-to-nearest int in low bits
    int ni = __float_as_int(z) - 0x4B400000;       // = round(t)
    float r = t - (z - 12582912.f);                // r in [-0.5, 0.5]
    float p = 0.0013333558f;
    p = fmaf(p, r, 0.009618130f);
    p = fmaf(p, r, 0.055504109f);
    p = fmaf(p, r, 0.240226507f);
    p = fmaf(p, r, 0.693147181f);
    p = fmaf(p, r, 1.0f);                          // 2^r
    return __int_as_float(__float_as_int(p) + (ni << 23));
}

__device__ __forceinline__ void mma_tf32(float* cc, const unsigned int* a,
                                         unsigned int b0, unsigned int b1) {
    asm volatile(
        "mma.sync.aligned.m16n8k8.row.col.f32.tf32.tf32.f32 "
        "{%0,%1,%2,%3}, {%4,%5,%6,%7}, {%8,%9}, {%0,%1,%2,%3};"
        : "+f"(cc[0]), "+f"(cc[1]), "+f"(cc[2]), "+f"(cc[3])
        : "r"(a[0]), "r"(a[1]), "r"(a[2]), "r"(a[3]), "r"(b0), "r"(b1));
}

__device__ __forceinline__ float bsum(float v, volatile float* sh) {
    #pragma unroll
    for (int o = 16; o; o >>= 1) v += __shfl_xor_sync(0xffffffffu, v, o);
    if ((threadIdx.x & 31) == 0) sh[threadIdx.x >> 5] = v;
    __syncthreads();
    if (threadIdx.x == 0) {
        float r = 0.f;
        #pragma unroll
        for (int i = 0; i < 8; i++) r += sh[i];
        sh[0] = r;
    }
    __syncthreads();
    float r = sh[0];
    __syncthreads();
    return r;
}

__device__ __forceinline__ void hadd(unsigned int* hh, unsigned int byte_or_dummy) {
    unsigned int peers = __match_any_sync(0xffffffffu, byte_or_dummy);
    int lane = threadIdx.x & 31;
    if (byte_or_dummy <= 255u && lane == (__ffs(peers) - 1))
        atomicAdd(&hh[byte_or_dummy], (unsigned int)__popc(peers));
}

__device__ __forceinline__ unsigned int warp_sel(const unsigned int* hh, int& rem) {
    int lane = threadIdx.x & 31;
    unsigned int bins[8], loc[8];
    #pragma unroll
    for (int k = 0; k < 8; k++) bins[k] = hh[lane * 8 + k];
    loc[7] = bins[7];
    #pragma unroll
    for (int k = 6; k >= 0; k--) loc[k] = loc[k + 1] + bins[k];
    unsigned int lsum = loc[0];
    unsigned int v = lsum;
    #pragma unroll
    for (int off = 1; off < 32; off <<= 1) {
        unsigned int o = __shfl_down_sync(0xffffffffu, v, off);
        if (lane + off < 32) v += o;
    }
    unsigned int above = v - lsum;
    int foundk = -1;
    int newrem = 0;
    #pragma unroll
    for (int k = 0; k < 8; k++) {
        unsigned int cum = loc[k] + above;
        unsigned int cumn = ((k < 7) ? loc[k + 1] : 0u) + above;
        if (cum >= (unsigned int)rem && cumn < (unsigned int)rem) {
            foundk = k;
            newrem = rem - (int)cumn;
        }
    }
    unsigned int ball = __ballot_sync(0xffffffffu, foundk >= 0);
    int src = __ffs(ball) - 1;
    unsigned int b = (unsigned int)__shfl_sync(0xffffffffu, lane * 8 + foundk, src);
    rem = __shfl_sync(0xffffffffu, newrem, src);
    return b;
}

// ---------------- K0 ----------------
__global__ void k_zero() {
    int i = blockIdx.x * 256 + threadIdx.x;
    if (i < BH * NN) { g_S[i] = 0.f; g_T[i] = 0.f; }
}

// ---------------- K1: QKV 1x1 conv via 2-term TF32 MMA (W hi-only, X hi+lo) ----------------
__global__ __launch_bounds__(256, 2) void k_qkv(const float* __restrict__ x,
                                                const float* __restrict__ w,
                                                const float* __restrict__ bias) {
    extern __shared__ float dsm[];
    float* ws2 = dsm;
    float* xs2 = dsm + 128 * QPAD;
    unsigned int* wrow = (unsigned int*)ws2;
    unsigned int* xrow = (unsigned int*)xs2;
    int b = blockIdx.z;
    int oc0 = blockIdx.y * 128, p0 = blockIdx.x * 128;
    int tid = threadIdx.x, wid = tid >> 5, lane = tid & 31;
    int g = lane >> 2, c = lane & 3;
    int R0 = (wid & 3) * 32, C0 = (wid >> 2) * 64;

    float acc[2][8][4] = {};
    for (int k0 = 0; k0 < 256; k0 += 32) {
        __syncthreads();
        #pragma unroll
        for (int l = 0; l < 4; l++) {
            int f = tid + 256 * l;
            int oc = f >> 3, k4 = f & 7;
            float4 v = *(const float4*)&w[(oc0 + oc) * 256 + k0 + k4 * 4];
            wrow[oc * QPAD + k4 * 4 + 0] = f2tf32(v.x);
            wrow[oc * QPAD + k4 * 4 + 1] = f2tf32(v.y);
            wrow[oc * QPAD + k4 * 4 + 2] = f2tf32(v.z);
            wrow[oc * QPAD + k4 * 4 + 3] = f2tf32(v.w);
        }
        #pragma unroll
        for (int l = 0; l < 4; l++) {
            int f = tid + 256 * l;
            int d = f >> 5, i4 = f & 31;
            int i = i4 * 4;
            int gp = p0 + i;
            float4 v = (gp < NN) ? *(const float4*)&x[(b * 256 + k0 + d) * NN + gp]
                                 : make_float4(0.f, 0.f, 0.f, 0.f);
            #pragma unroll
            for (int e = 0; e < 4; e++) {
                float xv = (&v.x)[e];
                unsigned int hi = f2tf32(xv);
                xrow[(i + e) * QPAD + d]      = hi;
                xrow[(i + e) * QPAD + 36 + d] = f2tf32(xv - __uint_as_float(hi));
            }
        }
        __syncthreads();
        #pragma unroll
        for (int ks = 0; ks < 4; ks++) {
            int kk = ks * 8;
            unsigned int ah[2][4];
            #pragma unroll
            for (int mt = 0; mt < 2; mt++) {
                int rb = R0 + mt * 16;
                ah[mt][0] = wrow[(rb + g) * QPAD + kk + c];
                ah[mt][1] = wrow[(rb + 8 + g) * QPAD + kk + c];
                ah[mt][2] = wrow[(rb + g) * QPAD + kk + c + 4];
                ah[mt][3] = wrow[(rb + 8 + g) * QPAD + kk + c + 4];
            }
            #pragma unroll
            for (int p = 0; p < 2; p++) {
                int boff = p * 36;
                #pragma unroll
                for (int nt = 0; nt < 8; nt++) {
                    int n0 = C0 + nt * 8 + g;
                    unsigned int b0 = xrow[n0 * QPAD + boff + kk + c];
                    unsigned int b1 = xrow[n0 * QPAD + boff + kk + c + 4];
                    mma_tf32(acc[0][nt], ah[0], b0, b1);
                    mma_tf32(acc[1][nt], ah[1], b0, b1);
                }
            }
        }
    }
    #pragma unroll
    for (int mt = 0; mt < 2; mt++) {
        #pragma unroll
        for (int v = 0; v < 2; v++) {
            int row = oc0 + R0 + mt * 16 + v * 8 + g;
            float bv = bias[row];
            #pragma unroll
            for (int nt = 0; nt < 8; nt++) {
                int col = p0 + C0 + nt * 8 + 2 * c;
                if (col < NN)
                    *(float2*)&g_qkv0[(b * C3 + row) * NN + col] =
                        make_float2(acc[mt][nt][2 * v] + bv, acc[mt][nt][2 * v + 1] + bv);
            }
        }
    }
}
#define QK_SMEM (2 * 128 * QPAD * 4)

// ---------------- K2: depthwise 3x3, smem-tiled per (b,channel) ----------------
__global__ __launch_bounds__(256) void k_dw(const float* __restrict__ pw,
                                            const float* __restrict__ pb) {
    __shared__ float img[NN];
    int bc = blockIdx.x;
    int ch = bc % C3;
    const float* src = g_qkv0 + (size_t)bc * NN;
    int tid = threadIdx.x;
    #pragma unroll
    for (int l = 0; l < 2; l++) {
        int i = tid + 256 * l;
        if (i < 400) ((float4*)img)[i] = ((const float4*)src)[i];
    }
    __syncthreads();
    float w0 = pw[ch * 9 + 0], w1 = pw[ch * 9 + 1], w2 = pw[ch * 9 + 2];
    float w3 = pw[ch * 9 + 3], w4 = pw[ch * 9 + 4], w5 = pw[ch * 9 + 5];
    float w6 = pw[ch * 9 + 6], w7 = pw[ch * 9 + 7], w8 = pw[ch * 9 + 8];
    float bv = pb[ch];
    float* dst = g_qkv1 + (size_t)bc * NN;
    #pragma unroll
    for (int l = 0; l < 7; l++) {
        int i = tid + 256 * l;
        if (i >= NN) break;
        int y = i / 40, x = i - y * 40;
        bool yn = y > 0, ys = y < 39, xw = x > 0, xe = x < 39;
        float s = bv + w4 * img[i];
        if (yn) {
            if (xw) s += w0 * img[i - 41];
            s += w1 * img[i - 40];
            if (xe) s += w2 * img[i - 39];
        }
        if (xw) s += w3 * img[i - 1];
        if (xe) s += w5 * img[i + 1];
        if (ys) {
            if (xw) s += w6 * img[i + 39];
            s += w7 * img[i + 40];
            if (xe) s += w8 * img[i + 41];
        }
        dst[i] = s;
    }
}

// ---------------- K3: e = exp(scale*QK^T) via 2-term TF32 (Q hi-only, K hi+lo) ----------------
__global__ __launch_bounds__(256, 2) void k_qk() {
    extern __shared__ float dsm[];
    float* qs2 = dsm;
    float* ks2 = dsm + 128 * QPAD;
    int bh = blockIdx.z;
    int b = bh >> 3, h = bh & 7;
    int i0 = blockIdx.y * 128, j0 = blockIdx.x * 128;
    int tid = threadIdx.x, wid = tid >> 5, lane = tid & 31;
    int g = lane >> 2, c = lane & 3;
    int R0 = (wid & 3) * 32, C0 = (wid >> 2) * 64;
    const float* qp = g_qkv1 + (b * C3 + h * HD) * NN;
    const float* kp = g_qkv1 + (b * C3 + 256 + h * HD) * NN;

    #pragma unroll
    for (int l = 0; l < 4; l++) {
        int f = tid + 256 * l;
        int d = f >> 5, i4 = f & 31;
        int i = i4 * 4;
        int gi = i0 + i, gj = j0 + i;
        float4 vq = (gi < NN) ? *(const float4*)&qp[d * NN + gi] : make_float4(0.f, 0.f, 0.f, 0.f);
        float4 vk = (gj < NN) ? *(const float4*)&kp[d * NN + gj] : make_float4(0.f, 0.f, 0.f, 0.f);
        #pragma unroll
        for (int e = 0; e < 4; e++) {
            ((unsigned int*)qs2)[(i + e) * QPAD + d] = f2tf32((&vq.x)[e]);
            float xk = (&vk.x)[e];
            unsigned int kh = f2tf32(xk);
            ((unsigned int*)ks2)[(i + e) * QPAD + d]      = kh;
            ((unsigned int*)ks2)[(i + e) * QPAD + 36 + d] = f2tf32(xk - __uint_as_float(kh));
        }
    }
    __syncthreads();

    const unsigned int* qrow = (const unsigned int*)qs2;
    const unsigned int* krow = (const unsigned int*)ks2;
    float acc[2][8][4] = {};
    #pragma unroll
    for (int ks = 0; ks < 4; ks++) {
        int k0 = ks * 8;
        unsigned int ah[2][4];
        #pragma unroll
        for (int mt = 0; mt < 2; mt++) {
            int rb = R0 + mt * 16;
            ah[mt][0] = qrow[(rb + g) * QPAD + k0 + c];
            ah[mt][1] = qrow[(rb + 8 + g) * QPAD + k0 + c];
            ah[mt][2] = qrow[(rb + g) * QPAD + k0 + c + 4];
            ah[mt][3] = qrow[(rb + 8 + g) * QPAD + k0 + c + 4];
        }
        #pragma unroll
        for (int p = 0; p < 2; p++) {
            int boff = p * 36;
            #pragma unroll
            for (int nt = 0; nt < 8; nt++) {
                int n0 = C0 + nt * 8 + g;
                unsigned int b0 = krow[n0 * QPAD + boff + k0 + c];
                unsigned int b1 = krow[n0 * QPAD + boff + k0 + c + 4];
                mma_tf32(acc[0][nt], ah[0], b0, b1);
                mma_tf32(acc[1][nt], ah[1], b0, b1);
            }
        }
    }

    float* outp = g_attn + (size_t)bh * NN * NN;
    #pragma unroll
    for (int mt = 0; mt < 2; mt++) {
        #pragma unroll
        for (int v = 0; v < 2; v++) {
            int row = i0 + R0 + mt * 16 + v * 8 + g;
            bool rok = row < NN;
            float se = 0.f, te = 0.f;
            #pragma unroll
            for (int nt = 0; nt < 8; nt++) {
                int col = j0 + C0 + nt * 8 + 2 * c;
                float a0 = acc[mt][nt][2 * v] * SCALE;
                float a1 = acc[mt][nt][2 * v + 1] * SCALE;
                float e0 = fexp(a0), e1 = fexp(a1);
                if (rok && col < NN) {
                    *(float2*)&outp[(size_t)row * NN + col] = make_float2(e0, e1);
                    se += e0 + e1;
                    te += a0 * e0 + a1 * e1;
                }
            }
            se += __shfl_xor_sync(0xffffffffu, se, 1);
            te += __shfl_xor_sync(0xffffffffu, te, 1);
            se += __shfl_xor_sync(0xffffffffu, se, 2);
            te += __shfl_xor_sync(0xffffffffu, te, 2);
            if (c == 0 && rok) {
                atomicAdd(&g_S[bh * NN + row], se);
                atomicAdd(&g_T[bh * NN + row], te);
            }
        }
    }
}

// ---------------- K4: entropy gate ----------------
__global__ void k_gate(const float* __restrict__ g1w, const float* __restrict__ g1b,
                       const float* __restrict__ g2w, const float* __restrict__ g2b) {
    int bh = blockIdx.x;
    __shared__ float sh[8];
    float s = 0.f;
    for (int i = threadIdx.x; i < NN; i += 256) {
        float S = g_S[bh * NN + i];
        float T = g_T[bh * NN + i];
        s += logf(S) - T / S;
    }
    s = bsum(s, sh);
    if (threadIdx.x == 0) {
        float e = s / (float)NN;
        float z = g2b[0];
        #pragma unroll
        for (int i = 0; i < 16; i++) {
            float hid = fmaxf(e * g1w[i] + g1b[i], 0.f);
            z += hid * g2w[i];
        }
        float ratio = 1.f / (1.f + expf(-z)) * 0.9f + 0.1f;
        int keep = (int)ceilf(ratio * (float)NN);
        keep = min(max(keep, 1), NN);
        g_keep[bh] = keep;
    }
}

// ---------------- K5: fused select + PV (PV 2-term TF32) ----------------
#define SPV_SMEM 67584
#define PPAD 132
__global__ __launch_bounds__(256) void k_spv() {
    extern __shared__ float pool[];
    unsigned int* keybuf = (unsigned int*)pool;
    unsigned int* histb  = (unsigned int*)pool + 8 * 1600;
    unsigned int* candb  = (unsigned int*)pool + 8 * 1600 + 8 * 256;
    float* ps  = pool;                           // [64][PPAD] (hi only used)
    float* vs  = pool + 64 * PPAD;               // [32][PPAD]
    float* red = pool + 64 * PPAD + 32 * PPAD;   // [64][34]
    __shared__ float thf[64];
    __shared__ float ivs[64];

    int bh = blockIdx.y;
    int b = bh >> 3, h = bh & 7;
    int row0 = blockIdx.x * 64;
    int tid = threadIdx.x, w = tid >> 5, lane = tid & 31;
    unsigned int lmask = (1u << lane) - 1u;
    const float* A = g_attn + (size_t)bh * NN * NN;
    int keep = g_keep[bh];

    unsigned int* kv = keybuf + w * 1600;
    unsigned int* hh = histb + w * 256;
    unsigned int* cd = candb + w * 256;

    // ---- phase 1: warp-per-row select (R11 proven) ----
    for (int i = 0; i < 8; i++) {
        int r = w * 8 + i;
        const uint4* src = (const uint4*)(A + (size_t)(row0 + r) * NN);
        ((uint4*)hh)[lane]      = make_uint4(0u, 0u, 0u, 0u);
        ((uint4*)hh)[lane + 32] = make_uint4(0u, 0u, 0u, 0u);
        __syncwarp();
        float Sall = 0.f;
        unsigned int andb = 0xFFu, orb = 0u;
        for (int t = 0; t < 13; t++) {
            int idx = t * 32 + lane;
            bool ok = idx < 400;
            if (ok) {
                uint4 kk = src[idx];
                kk.x |= 0x80000000u; kk.y |= 0x80000000u;
                kk.z |= 0x80000000u; kk.w |= 0x80000000u;
                ((uint4*)kv)[idx] = kk;
                Sall += key2f(kk.x) + key2f(kk.y) + key2f(kk.z) + key2f(kk.w);
                andb &= (kk.x >> 24) & (kk.y >> 24) & (kk.z >> 24) & (kk.w >> 24);
                orb  |= (kk.x >> 24) | (kk.y >> 24) | (kk.z >> 24) | (kk.w >> 24);
            }
        }
        #pragma unroll
        for (int o = 16; o; o >>= 1) {
            Sall += __shfl_xor_sync(0xffffffffu, Sall, o);
            andb &= __shfl_xor_sync(0xffffffffu, andb, o);
            orb  |= __shfl_xor_sync(0xffffffffu, orb, o);
        }
        if (keep == NN) {
            if (lane == 0) { thf[r] = 0.f; ivs[r] = 1.f / Sall; }
            continue;
        }
        __syncwarp();
        int rem = keep;
        unsigned int pref16;
        if (andb == orb) {
            for (int t = 0; t < 13; t++) {
                int idx = t * 32 + lane;
                bool ok = idx < 400;
                uint4 kk = ok ? ((const uint4*)kv)[idx] : make_uint4(0u, 0u, 0u, 0u);
                hadd(hh, ok ? ((kk.x >> 16) & 0xFFu) : 0xFFFFFFFFu);
                hadd(hh, ok ? ((kk.y >> 16) & 0xFFu) : 0xFFFFFFFFu);
                hadd(hh, ok ? ((kk.z >> 16) & 0xFFu) : 0xFFFFFFFFu);
                hadd(hh, ok ? ((kk.w >> 16) & 0xFFu) : 0xFFFFFFFFu);
            }
            __syncwarp();
            unsigned int b2 = warp_sel(hh, rem);
            pref16 = (andb << 8) | b2;
        } else {
            for (int t = 0; t < 50; t++)
                hadd(hh, kv[t * 32 + lane] >> 24);
            __syncwarp();
            unsigned int b3 = warp_sel(hh, rem);
            ((uint4*)hh)[lane]      = make_uint4(0u, 0u, 0u, 0u);
            ((uint4*)hh)[lane + 32] = make_uint4(0u, 0u, 0u, 0u);
            __syncwarp();
            for (int t = 0; t < 50; t++) {
                unsigned int key = kv[t * 32 + lane];
                hadd(hh, ((key >> 24) == b3) ? ((key >> 16) & 0xFFu) : 0xFFFFFFFFu);
            }
            __syncwarp();
            unsigned int b2 = warp_sel(hh, rem);
            pref16 = (b3 << 8) | b2;
        }
        int cnt = 0;
        float sum_hi = 0.f;
        for (int t = 0; t < 13; t++) {
            int idx = t * 32 + lane;
            bool ok = idx < 400;
            uint4 kk = ok ? ((const uint4*)kv)[idx] : make_uint4(0u, 0u, 0u, 0u);
            #define CPROC(KEY)                                                      \
            {                                                                       \
                unsigned int hi = (KEY) >> 16;                                      \
                bool isc = ok && (hi == pref16);                                    \
                if (ok && hi > pref16) sum_hi += key2f(KEY);                        \
                unsigned int bal = __ballot_sync(0xffffffffu, isc);                 \
                if (isc) {                                                          \
                    int pos = cnt + __popc(bal & lmask);                            \
                    if (pos < 256) cd[pos] = (KEY);                                 \
                }                                                                   \
                cnt += __popc(bal);                                                 \
            }
            CPROC(kk.x) CPROC(kk.y) CPROC(kk.z) CPROC(kk.w)
            #undef CPROC
        }
        __syncwarp();
        unsigned int pref;
        float Spart;
        if (cnt <= 256) {
            int iters = (cnt + 31) >> 5;
            ((uint4*)hh)[lane]      = make_uint4(0u, 0u, 0u, 0u);
            ((uint4*)hh)[lane + 32] = make_uint4(0u, 0u, 0u, 0u);
            __syncwarp();
            for (int t = 0; t < iters; t++) {
                int idx = t * 32 + lane;
                bool ok = idx < cnt;
                unsigned int key = ok ? cd[idx] : 0u;
                hadd(hh, ok ? ((key >> 8) & 0xFFu) : 0xFFFFFFFFu);
            }
            __syncwarp();
            unsigned int b1 = warp_sel(hh, rem);
            ((uint4*)hh)[lane]      = make_uint4(0u, 0u, 0u, 0u);
            ((uint4*)hh)[lane + 32] = make_uint4(0u, 0u, 0u, 0u);
            __syncwarp();
            for (int t = 0; t < iters; t++) {
                int idx = t * 32 + lane;
                bool ok = idx < cnt;
                unsigned int key = ok ? cd[idx] : 0u;
                hadd(hh, (ok && ((key >> 8) & 0xFFu) == b1) ? (key & 0xFFu) : 0xFFFFFFFFu);
            }
            __syncwarp();
            unsigned int b0 = warp_sel(hh, rem);
            pref = (pref16 << 16) | (b1 << 8) | b0;
            float Sc = 0.f;
            for (int t = 0; t < iters; t++) {
                int idx = t * 32 + lane;
                if (idx < cnt) {
                    unsigned int key = cd[idx];
                    if (key >= pref) Sc += key2f(key);
                }
            }
            Spart = sum_hi + Sc;
        } else {
            ((uint4*)hh)[lane]      = make_uint4(0u, 0u, 0u, 0u);
            ((uint4*)hh)[lane + 32] = make_uint4(0u, 0u, 0u, 0u);
            __syncwarp();
            for (int t = 0; t < 50; t++) {
                int idx = t * 32 + lane;
                unsigned int key = kv[idx];
                hadd(hh, ((key >> 16) == pref16) ? ((key >> 8) & 0xFFu) : 0xFFFFFFFFu);
            }
            __syncwarp();
            unsigned int b1 = warp_sel(hh, rem);
            unsigned int pref24 = (pref16 << 8) | b1;
            ((uint4*)hh)[lane]      = make_uint4(0u, 0u, 0u, 0u);
            ((uint4*)hh)[lane + 32] = make_uint4(0u, 0u, 0u, 0u);
            __syncwarp();
            for (int t = 0; t < 50; t++) {
                int idx = t * 32 + lane;
                unsigned int key = kv[idx];
                hadd(hh, ((key >> 8) == pref24) ? (key & 0xFFu) : 0xFFFFFFFFu);
            }
            __syncwarp();
            unsigned int b0 = warp_sel(hh, rem);
            pref = (pref24 << 8) | b0;
            float Sf = 0.f;
            for (int t = 0; t < 50; t++) {
                unsigned int key = kv[t * 32 + lane];
                if (key >= pref) Sf += key2f(key);
            }
            Spart = Sf;
        }
        #pragma unroll
        for (int o = 16; o; o >>= 1) Spart += __shfl_xor_sync(0xffffffffu, Spart, o);
        if (lane == 0) {
            thf[r] = key2f(pref);
            ivs[r] = 1.f / Spart;
        }
    }
    __syncthreads();

    // ---- phase 2: out = P @ V^T via TF32 MMA (P hi-only, V hi+lo), K split ----
    const float* V = g_qkv1 + (b * C3 + 512 + h * HD) * NN;
    unsigned int* psu = (unsigned int*)ps;
    unsigned int* vsu = (unsigned int*)vs;
    int g = lane >> 2, c = lane & 3;
    int kg = w >> 2;
    int mt = w & 3;
    float acc[4][4] = {};
    for (int j0 = 0; j0 < NN; j0 += 64) {
        __syncthreads();
        #pragma unroll
        for (int l = 0; l < 4; l++) {
            int f = tid + 256 * l;
            int rr = f >> 4, c4 = f & 15;
            float4 e4 = *(const float4*)&A[(size_t)(row0 + rr) * NN + j0 + c4 * 4];
            float th = thf[rr], ivv = ivs[rr];
            float p0 = (e4.x >= th) ? e4.x * ivv : 0.f;
            float p1 = (e4.y >= th) ? e4.y * ivv : 0.f;
            float p2 = (e4.z >= th) ? e4.z * ivv : 0.f;
            float p3 = (e4.w >= th) ? e4.w * ivv : 0.f;
            psu[rr * PPAD + c4 * 4 + 0] = f2tf32(p0);
            psu[rr * PPAD + c4 * 4 + 1] = f2tf32(p1);
            psu[rr * PPAD + c4 * 4 + 2] = f2tf32(p2);
            psu[rr * PPAD + c4 * 4 + 3] = f2tf32(p3);
        }
        #pragma unroll
        for (int l = 0; l < 2; l++) {
            int f = tid + 256 * l;
            int d = f >> 4, j4 = f & 15;
            float4 vv = *(const float4*)&V[d * NN + j0 + j4 * 4];
            unsigned int h0 = f2tf32(vv.x), h1 = f2tf32(vv.y);
            unsigned int h2 = f2tf32(vv.z), h3 = f2tf32(vv.w);
            vsu[d * PPAD + j4 * 4 + 0] = h0;
            vsu[d * PPAD + j4 * 4 + 1] = h1;
            vsu[d * PPAD + j4 * 4 + 2] = h2;
            vsu[d * PPAD + j4 * 4 + 3] = h3;
            vsu[d * PPAD + 68 + j4 * 4 + 0] = f2tf32(vv.x - __uint_as_float(h0));
            vsu[d * PPAD + 68 + j4 * 4 + 1] = f2tf32(vv.y - __uint_as_float(h1));
            vsu[d * PPAD + 68 + j4 * 4 + 2] = f2tf32(vv.z - __uint_as_float(h2));
            vsu[d * PPAD + 68 + j4 * 4 + 3] = f2tf32(vv.w - __uint_as_float(h3));
        }
        __syncthreads();
        #pragma unroll
        for (int ks = 0; ks < 4; ks++) {
            int k = kg * 32 + ks * 8;
            int rb = mt * 16;
            unsigned int ah[4];
            ah[0] = psu[(rb + g) * PPAD + k + c];
            ah[1] = psu[(rb + 8 + g) * PPAD + k + c];
            ah[2] = psu[(rb + g) * PPAD + k + c + 4];
            ah[3] = psu[(rb + 8 + g) * PPAD + k + c + 4];
            #pragma unroll
            for (int nt = 0; nt < 4; nt++) {
                int n0 = nt * 8 + g;
                unsigned int b0h = vsu[n0 * PPAD + k + c];
                unsigned int b1h = vsu[n0 * PPAD + k + c + 4];
                unsigned int b0l = vsu[n0 * PPAD + 68 + k + c];
                unsigned int b1l = vsu[n0 * PPAD + 68 + k + c + 4];
                mma_tf32(acc[nt], ah, b0h, b1h);
                mma_tf32(acc[nt], ah, b0l, b1l);
            }
        }
    }
    __syncthreads();
    if (kg == 1) {
        #pragma unroll
        for (int nt = 0; nt < 4; nt++)
            #pragma unroll
            for (int v = 0; v < 2; v++) {
                int r = mt * 16 + v * 8 + g;
                *(float2*)&red[r * 34 + nt * 8 + 2 * c] =
                    make_float2(acc[nt][2 * v], acc[nt][2 * v + 1]);
            }
    }
    __syncthreads();
    if (kg == 0) {
        #pragma unroll
        for (int nt = 0; nt < 4; nt++)
            #pragma unroll
            for (int v = 0; v < 2; v++) {
                int r = mt * 16 + v * 8 + g;
                float2 o = *(float2*)&red[r * 34 + nt * 8 + 2 * c];
                o.x += acc[nt][2 * v];
                o.y += acc[nt][2 * v + 1];
                *(float2*)&g_attout[(size_t)(b * NN + row0 + r) * CC + h * HD + nt * 8 + 2 * c] = o;
            }
    }
}

// ---------------- K7: output projection ----------------
__global__ void k_proj(const float* __restrict__ w, const float* __restrict__ bias,
                       float* __restrict__ out) {
    __shared__ float ws[32][65];
    __shared__ float as[32][65];
    int b = blockIdx.z;
    int co0 = blockIdx.y * 64, p0 = blockIdx.x * 64;
    int tid = threadIdx.x, tx = tid & 15, ty = tid >> 4;
    float acc[4][4] = {};
    for (int k0 = 0; k0 < 256; k0 += 32) {
        #pragma unroll
        for (int l = 0; l < 8; l++) {
            int idx = tid + 256 * l;
            int r = idx >> 5, c = idx & 31;
            ws[c][r] = w[(co0 + r) * 256 + k0 + c];
        }
        #pragma unroll
        for (int l = 0; l < 8; l++) {
            int idx = tid + 256 * l;
            int p = idx >> 5, c = idx & 31;
            as[c][p] = g_attout[(size_t)(b * NN + p0 + p) * CC + k0 + c];
        }
        __syncthreads();
        #pragma unroll
        for (int kk = 0; kk < 32; kk++) {
            float a[4], bv[4];
            #pragma unroll
            for (int i = 0; i < 4; i++) a[i] = ws[kk][ty * 4 + i];
            #pragma unroll
            for (int j = 0; j < 4; j++) bv[j] = as[kk][tx * 4 + j];
            #pragma unroll
            for (int i = 0; i < 4; i++)
                #pragma unroll
                for (int j = 0; j < 4; j++) acc[i][j] += a[i] * bv[j];
        }
        __syncthreads();
    }
    #pragma unroll
    for (int i = 0; i < 4; i++) {
        int co = co0 + ty * 4 + i;
        float bv = bias[co];
        #pragma unroll
        for (int j = 0; j < 4; j++)
            out[(b * CC + co) * NN + p0 + tx * 4 + j] = acc[i][j] + bv;
    }
}

extern "C" void kernel_launch(void* const* d_in, const int* in_sizes, int n_in,
                              void* d_out, int out_size) {
    const float* x      = (const float*)d_in[0];
    const float* qkv_w  = (const float*)d_in[1];
    const float* qkv_b  = (const float*)d_in[2];
    const float* pos_w  = (const float*)d_in[3];
    const float* pos_b  = (const float*)d_in[4];
    const float* proj_w = (const float*)d_in[5];
    const float* proj_b = (const float*)d_in[6];
    const float* g1w    = (const float*)d_in[7];
    const float* g1b    = (const float*)d_in[8];
    const float* g2w    = (const float*)d_in[9];
    const float* g2b    = (const float*)d_in[10];
    float* out = (float*)d_out;

    static int configured = 0;
    if (!configured) {
        cudaFuncSetAttribute(k_qk, cudaFuncAttributeMaxDynamicSharedMemorySize, QK_SMEM);
        cudaFuncSetAttribute(k_qkv, cudaFuncAttributeMaxDynamicSharedMemorySize, QK_SMEM);
        cudaFuncSetAttribute(k_spv, cudaFuncAttributeMaxDynamicSharedMemorySize, SPV_SMEM);
        configured = 1;
    }

    k_zero<<<(BH * NN + 255) / 256, 256>>>();
    k_qkv<<<dim3(13, 6, 2), 256, QK_SMEM>>>(x, qkv_w, qkv_b);
    k_dw<<<BB * C3, 256>>>(pos_w, pos_b);
    k_qk<<<dim3(13, 13, 16), 256, QK_SMEM>>>();
    k_gate<<<BH, 256>>>(g1w, g1b, g2w, g2b);
    k_spv<<<dim3(25, 16), 256, SPV_SMEM>>>();
    k_proj<<<dim3(25, 4, 2), 256>>>(proj_w, proj_b, out);
}

// round 15
// speedup vs baseline: 1.0082x; 1.0082x over previous
#include <cuda_runtime.h>
#include <math.h>

#define BB 2
#define CC 256
#define NHEADS 8
#define HD 32
#define NN 1600
#define C3 768
#define BH 16
#define SCALE 0.17677669529663687f  // 1/sqrt(32)
#define QPAD 73

// ---------------- scratch ----------------
__device__ float g_qkv0[BB * C3 * NN];
__device__ float g_qkv1[BB * C3 * NN];
__device__ float g_attn[(size_t)BH * NN * NN];     // e = exp(logit), all > 0
__device__ float g_S[BH * NN];
__device__ float g_T[BH * NN];
__device__ int   g_keep[BH];
__device__ float g_attout[BB * NN * CC];

// ---------------- helpers ----------------
__device__ __forceinline__ float key2f(unsigned int k) {
    return __uint_as_float(k ^ 0x80000000u);
}

__device__ __forceinline__ unsigned int f2tf32(float x) {
    unsigned int r;
    asm("cvt.rna.tf32.f32 %0, %1;" : "=r"(r) : "f"(x));
    return r;
}

__device__ __forceinline__ void mma_tf32(float* cc, const unsigned int* a,
                                         unsigned int b0, unsigned int b1) {
    asm volatile(
        "mma.sync.aligned.m16n8k8.row.col.f32.tf32.tf32.f32 "
        "{%0,%1,%2,%3}, {%4,%5,%6,%7}, {%8,%9}, {%0,%1,%2,%3};"
        : "+f"(cc[0]), "+f"(cc[1]), "+f"(cc[2]), "+f"(cc[3])
        : "r"(a[0]), "r"(a[1]), "r"(a[2]), "r"(a[3]), "r"(b0), "r"(b1));
}

__device__ __forceinline__ float bsum(float v, volatile float* sh) {
    #pragma unroll
    for (int o = 16; o; o >>= 1) v += __shfl_xor_sync(0xffffffffu, v, o);
    if ((threadIdx.x & 31) == 0) sh[threadIdx.x >> 5] = v;
    __syncthreads();
    if (threadIdx.x == 0) {
        float r = 0.f;
        #pragma unroll
        for (int i = 0; i < 8; i++) r += sh[i];
        sh[0] = r;
    }
    __syncthreads();
    float r = sh[0];
    __syncthreads();
    return r;
}

// match-aggregated add: for clustered bytes only
__device__ __forceinline__ void hadd(unsigned int* hh, unsigned int byte_or_dummy) {
    unsigned int peers = __match_any_sync(0xffffffffu, byte_or_dummy);
    int lane = threadIdx.x & 31;
    if (byte_or_dummy <= 255u && lane == (__ffs(peers) - 1))
        atomicAdd(&hh[byte_or_dummy], (unsigned int)__popc(peers));
}

__device__ __forceinline__ unsigned int warp_sel(const unsigned int* hh, int& rem) {
    int lane = threadIdx.x & 31;
    unsigned int bins[8], loc[8];
    #pragma unroll
    for (int k = 0; k < 8; k++) bins[k] = hh[lane * 8 + k];
    loc[7] = bins[7];
    #pragma unroll
    for (int k = 6; k >= 0; k--) loc[k] = loc[k + 1] + bins[k];
    unsigned int lsum = loc[0];
    unsigned int v = lsum;
    #pragma unroll
    for (int off = 1; off < 32; off <<= 1) {
        unsigned int o = __shfl_down_sync(0xffffffffu, v, off);
        if (lane + off < 32) v += o;
    }
    unsigned int above = v - lsum;
    int foundk = -1;
    int newrem = 0;
    #pragma unroll
    for (int k = 0; k < 8; k++) {
        unsigned int cum = loc[k] + above;
        unsigned int cumn = ((k < 7) ? loc[k + 1] : 0u) + above;
        if (cum >= (unsigned int)rem && cumn < (unsigned int)rem) {
            foundk = k;
            newrem = rem - (int)cumn;
        }
    }
    unsigned int ball = __ballot_sync(0xffffffffu, foundk >= 0);
    int src = __ffs(ball) - 1;
    unsigned int b = (unsigned int)__shfl_sync(0xffffffffu, lane * 8 + foundk, src);
    rem = __shfl_sync(0xffffffffu, newrem, src);
    return b;
}

// ---------------- K0 ----------------
__global__ void k_zero() {
    int i = blockIdx.x * 256 + threadIdx.x;
    if (i < BH * NN) { g_S[i] = 0.f; g_T[i] = 0.f; }
}

// ---------------- K1: QKV 1x1 conv via 2-term TF32 MMA (W hi-only, X hi+lo) ----------------
__global__ __launch_bounds__(256, 2) void k_qkv(const float* __restrict__ x,
                                                const float* __restrict__ w,
                                                const float* __restrict__ bias) {
    extern __shared__ float dsm[];
    float* ws2 = dsm;
    float* xs2 = dsm + 128 * QPAD;
    unsigned int* wrow = (unsigned int*)ws2;
    unsigned int* xrow = (unsigned int*)xs2;
    int b = blockIdx.z;
    int oc0 = blockIdx.y * 128, p0 = blockIdx.x * 128;
    int tid = threadIdx.x, wid = tid >> 5, lane = tid & 31;
    int g = lane >> 2, c = lane & 3;
    int R0 = (wid & 3) * 32, C0 = (wid >> 2) * 64;

    float acc[2][8][4] = {};
    for (int k0 = 0; k0 < 256; k0 += 32) {
        __syncthreads();
        #pragma unroll
        for (int l = 0; l < 4; l++) {
            int f = tid + 256 * l;
            int oc = f >> 3, k4 = f & 7;
            float4 v = *(const float4*)&w[(oc0 + oc) * 256 + k0 + k4 * 4];
            wrow[oc * QPAD + k4 * 4 + 0] = f2tf32(v.x);
            wrow[oc * QPAD + k4 * 4 + 1] = f2tf32(v.y);
            wrow[oc * QPAD + k4 * 4 + 2] = f2tf32(v.z);
            wrow[oc * QPAD + k4 * 4 + 3] = f2tf32(v.w);
        }
        #pragma unroll
        for (int l = 0; l < 4; l++) {
            int f = tid + 256 * l;
            int d = f >> 5, i4 = f & 31;
            int i = i4 * 4;
            int gp = p0 + i;
            float4 v = (gp < NN) ? *(const float4*)&x[(b * 256 + k0 + d) * NN + gp]
                                 : make_float4(0.f, 0.f, 0.f, 0.f);
            #pragma unroll
            for (int e = 0; e < 4; e++) {
                float xv = (&v.x)[e];
                unsigned int hi = f2tf32(xv);
                xrow[(i + e) * QPAD + d]      = hi;
                xrow[(i + e) * QPAD + 36 + d] = f2tf32(xv - __uint_as_float(hi));
            }
        }
        __syncthreads();
        #pragma unroll
        for (int ks = 0; ks < 4; ks++) {
            int kk = ks * 8;
            unsigned int ah[2][4];
            #pragma unroll
            for (int mt = 0; mt < 2; mt++) {
                int rb = R0 + mt * 16;
                ah[mt][0] = wrow[(rb + g) * QPAD + kk + c];
                ah[mt][1] = wrow[(rb + 8 + g) * QPAD + kk + c];
                ah[mt][2] = wrow[(rb + g) * QPAD + kk + c + 4];
                ah[mt][3] = wrow[(rb + 8 + g) * QPAD + kk + c + 4];
            }
            #pragma unroll
            for (int p = 0; p < 2; p++) {
                int boff = p * 36;
                #pragma unroll
                for (int nt = 0; nt < 8; nt++) {
                    int n0 = C0 + nt * 8 + g;
                    unsigned int b0 = xrow[n0 * QPAD + boff + kk + c];
                    unsigned int b1 = xrow[n0 * QPAD + boff + kk + c + 4];
                    mma_tf32(acc[0][nt], ah[0], b0, b1);
                    mma_tf32(acc[1][nt], ah[1], b0, b1);
                }
            }
        }
    }
    #pragma unroll
    for (int mt = 0; mt < 2; mt++) {
        #pragma unroll
        for (int v = 0; v < 2; v++) {
            int row = oc0 + R0 + mt * 16 + v * 8 + g;
            float bv = bias[row];
            #pragma unroll
            for (int nt = 0; nt < 8; nt++) {
                int col = p0 + C0 + nt * 8 + 2 * c;
                if (col < NN)
                    *(float2*)&g_qkv0[(b * C3 + row) * NN + col] =
                        make_float2(acc[mt][nt][2 * v] + bv, acc[mt][nt][2 * v + 1] + bv);
            }
        }
    }
}
#define QK_SMEM (2 * 128 * QPAD * 4)

// ---------------- K2: depthwise 3x3, smem-tiled per (b,channel) ----------------
__global__ __launch_bounds__(256) void k_dw(const float* __restrict__ pw,
                                            const float* __restrict__ pb) {
    __shared__ float img[NN];
    int bc = blockIdx.x;
    int ch = bc % C3;
    const float* src = g_qkv0 + (size_t)bc * NN;
    int tid = threadIdx.x;
    #pragma unroll
    for (int l = 0; l < 2; l++) {
        int i = tid + 256 * l;
        if (i < 400) ((float4*)img)[i] = ((const float4*)src)[i];
    }
    __syncthreads();
    float w0 = pw[ch * 9 + 0], w1 = pw[ch * 9 + 1], w2 = pw[ch * 9 + 2];
    float w3 = pw[ch * 9 + 3], w4 = pw[ch * 9 + 4], w5 = pw[ch * 9 + 5];
    float w6 = pw[ch * 9 + 6], w7 = pw[ch * 9 + 7], w8 = pw[ch * 9 + 8];
    float bv = pb[ch];
    float* dst = g_qkv1 + (size_t)bc * NN;
    #pragma unroll
    for (int l = 0; l < 7; l++) {
        int i = tid + 256 * l;
        if (i >= NN) break;
        int y = i / 40, x = i - y * 40;
        bool yn = y > 0, ys = y < 39, xw = x > 0, xe = x < 39;
        float s = bv + w4 * img[i];
        if (yn) {
            if (xw) s += w0 * img[i - 41];
            s += w1 * img[i - 40];
            if (xe) s += w2 * img[i - 39];
        }
        if (xw) s += w3 * img[i - 1];
        if (xe) s += w5 * img[i + 1];
        if (ys) {
            if (xw) s += w6 * img[i + 39];
            s += w7 * img[i + 40];
            if (xe) s += w8 * img[i + 41];
        }
        dst[i] = s;
    }
}

// ---------------- K3: e = exp(scale*QK^T) via 2-term TF32 (Q hi-only, K hi+lo) ----------------
__global__ __launch_bounds__(256, 2) void k_qk() {
    extern __shared__ float dsm[];
    float* qs2 = dsm;
    float* ks2 = dsm + 128 * QPAD;
    int bh = blockIdx.z;
    int b = bh >> 3, h = bh & 7;
    int i0 = blockIdx.y * 128, j0 = blockIdx.x * 128;
    int tid = threadIdx.x, wid = tid >> 5, lane = tid & 31;
    int g = lane >> 2, c = lane & 3;
    int R0 = (wid & 3) * 32, C0 = (wid >> 2) * 64;
    const float* qp = g_qkv1 + (b * C3 + h * HD) * NN;
    const float* kp = g_qkv1 + (b * C3 + 256 + h * HD) * NN;

    #pragma unroll
    for (int l = 0; l < 4; l++) {
        int f = tid + 256 * l;
        int d = f >> 5, i4 = f & 31;
        int i = i4 * 4;
        int gi = i0 + i, gj = j0 + i;
        float4 vq = (gi < NN) ? *(const float4*)&qp[d * NN + gi] : make_float4(0.f, 0.f, 0.f, 0.f);
        float4 vk = (gj < NN) ? *(const float4*)&kp[d * NN + gj] : make_float4(0.f, 0.f, 0.f, 0.f);
        #pragma unroll
        for (int e = 0; e < 4; e++) {
            ((unsigned int*)qs2)[(i + e) * QPAD + d] = f2tf32((&vq.x)[e]);
            float xk = (&vk.x)[e];
            unsigned int kh = f2tf32(xk);
            ((unsigned int*)ks2)[(i + e) * QPAD + d]      = kh;
            ((unsigned int*)ks2)[(i + e) * QPAD + 36 + d] = f2tf32(xk - __uint_as_float(kh));
        }
    }
    __syncthreads();

    const unsigned int* qrow = (const unsigned int*)qs2;
    const unsigned int* krow = (const unsigned int*)ks2;
    float acc[2][8][4] = {};
    #pragma unroll
    for (int ks = 0; ks < 4; ks++) {
        int k0 = ks * 8;
        unsigned int ah[2][4];
        #pragma unroll
        for (int mt = 0; mt < 2; mt++) {
            int rb = R0 + mt * 16;
            ah[mt][0] = qrow[(rb + g) * QPAD + k0 + c];
            ah[mt][1] = qrow[(rb + 8 + g) * QPAD + k0 + c];
            ah[mt][2] = qrow[(rb + g) * QPAD + k0 + c + 4];
            ah[mt][3] = qrow[(rb + 8 + g) * QPAD + k0 + c + 4];
        }
        #pragma unroll
        for (int p = 0; p < 2; p++) {
            int boff = p * 36;
            #pragma unroll
            for (int nt = 0; nt < 8; nt++) {
                int n0 = C0 + nt * 8 + g;
                unsigned int b0 = krow[n0 * QPAD + boff + k0 + c];
                unsigned int b1 = krow[n0 * QPAD + boff + k0 + c + 4];
                mma_tf32(acc[0][nt], ah[0], b0, b1);
                mma_tf32(acc[1][nt], ah[1], b0, b1);
            }
        }
    }

    float* outp = g_attn + (size_t)bh * NN * NN;
    #pragma unroll
    for (int mt = 0; mt < 2; mt++) {
        #pragma unroll
        for (int v = 0; v < 2; v++) {
            int row = i0 + R0 + mt * 16 + v * 8 + g;
            bool rok = row < NN;
            float se = 0.f, te = 0.f;
            #pragma unroll
            for (int nt = 0; nt < 8; nt++) {
                int col = j0 + C0 + nt * 8 + 2 * c;
                float a0 = acc[mt][nt][2 * v] * SCALE;
                float a1 = acc[mt][nt][2 * v + 1] * SCALE;
                float e0 = __expf(a0), e1 = __expf(a1);
                if (rok && col < NN) {
                    *(float2*)&outp[(size_t)row * NN + col] = make_float2(e0, e1);
                    se += e0 + e1;
                    te += a0 * e0 + a1 * e1;
                }
            }
            se += __shfl_xor_sync(0xffffffffu, se, 1);
            te += __shfl_xor_sync(0xffffffffu, te, 1);
            se += __shfl_xor_sync(0xffffffffu, se, 2);
            te += __shfl_xor_sync(0xffffffffu, te, 2);
            if (c == 0 && rok) {
                atomicAdd(&g_S[bh * NN + row], se);
                atomicAdd(&g_T[bh * NN + row], te);
            }
        }
    }
}

// ---------------- K4: entropy gate ----------------
__global__ void k_gate(const float* __restrict__ g1w, const float* __restrict__ g1b,
                       const float* __restrict__ g2w, const float* __restrict__ g2b) {
    int bh = blockIdx.x;
    __shared__ float sh[8];
    float s = 0.f;
    for (int i = threadIdx.x; i < NN; i += 256) {
        float S = g_S[bh * NN + i];
        float T = g_T[bh * NN + i];
        s += logf(S) - T / S;
    }
    s = bsum(s, sh);
    if (threadIdx.x == 0) {
        float e = s / (float)NN;
        float z = g2b[0];
        #pragma unroll
        for (int i = 0; i < 16; i++) {
            float hid = fmaxf(e * g1w[i] + g1b[i], 0.f);
            z += hid * g2w[i];
        }
        float ratio = 1.f / (1.f + expf(-z)) * 0.9f + 0.1f;
        int keep = (int)ceilf(ratio * (float)NN);
        keep = min(max(keep, 1), NN);
        g_keep[bh] = keep;
    }
}

// ---------------- K5: fused select + PV ----------------
#define SPV_SMEM 67584
#define PPAD 132
__global__ __launch_bounds__(256) void k_spv() {
    extern __shared__ float pool[];
    unsigned int* keybuf = (unsigned int*)pool;
    unsigned int* histb  = (unsigned int*)pool + 8 * 1600;
    unsigned int* candb  = (unsigned int*)pool + 8 * 1600 + 8 * 256;
    float* ps  = pool;                           // [64][PPAD] (hi only used)
    float* vs  = pool + 64 * PPAD;               // [32][PPAD]
    float* red = pool + 64 * PPAD + 32 * PPAD;   // [64][34]
    __shared__ float thf[64];
    __shared__ float ivs[64];

    int bh = blockIdx.y;
    int b = bh >> 3, h = bh & 7;
    int row0 = blockIdx.x * 64;
    int tid = threadIdx.x, w = tid >> 5, lane = tid & 31;
    unsigned int lmask = (1u << lane) - 1u;
    const float* A = g_attn + (size_t)bh * NN * NN;
    int keep = g_keep[bh];

    unsigned int* kv = keybuf + w * 1600;
    unsigned int* hh = histb + w * 256;
    unsigned int* cd = candb + w * 256;

    // ---- phase 1: warp-per-row select ----
    for (int i = 0; i < 8; i++) {
        int r = w * 8 + i;
        const uint4* src = (const uint4*)(A + (size_t)(row0 + r) * NN);
        ((uint4*)hh)[lane]      = make_uint4(0u, 0u, 0u, 0u);
        ((uint4*)hh)[lane + 32] = make_uint4(0u, 0u, 0u, 0u);
        __syncwarp();
        float Sall = 0.f;
        unsigned int andb = 0xFFu, orb = 0u;
        for (int t = 0; t < 13; t++) {
            int idx = t * 32 + lane;
            bool ok = idx < 400;
            if (ok) {
                uint4 kk = src[idx];
                kk.x |= 0x80000000u; kk.y |= 0x80000000u;
                kk.z |= 0x80000000u; kk.w |= 0x80000000u;
                ((uint4*)kv)[idx] = kk;
                Sall += key2f(kk.x) + key2f(kk.y) + key2f(kk.z) + key2f(kk.w);
                andb &= (kk.x >> 24) & (kk.y >> 24) & (kk.z >> 24) & (kk.w >> 24);
                orb  |= (kk.x >> 24) | (kk.y >> 24) | (kk.z >> 24) | (kk.w >> 24);
            }
        }
        #pragma unroll
        for (int o = 16; o; o >>= 1) {
            Sall += __shfl_xor_sync(0xffffffffu, Sall, o);
            andb &= __shfl_xor_sync(0xffffffffu, andb, o);
            orb  |= __shfl_xor_sync(0xffffffffu, orb, o);
        }
        if (keep == NN) {
            if (lane == 0) { thf[r] = 0.f; ivs[r] = 1.f / Sall; }
            continue;
        }
        __syncwarp();
        int rem = keep;
        unsigned int pref16;
        if (andb == orb) {
            // byte2 near-uniform: direct spread atomics (no match_any)
            for (int t = 0; t < 13; t++) {
                int idx = t * 32 + lane;
                if (idx < 400) {
                    uint4 kk = ((const uint4*)kv)[idx];
                    atomicAdd(&hh[(kk.x >> 16) & 0xFFu], 1u);
                    atomicAdd(&hh[(kk.y >> 16) & 0xFFu], 1u);
                    atomicAdd(&hh[(kk.z >> 16) & 0xFFu], 1u);
                    atomicAdd(&hh[(kk.w >> 16) & 0xFFu], 1u);
                }
            }
            __syncwarp();
            unsigned int b2 = warp_sel(hh, rem);
            pref16 = (andb << 8) | b2;
        } else {
            // rare fallback: clustered byte3 -> keep match aggregation
            for (int t = 0; t < 50; t++)
                hadd(hh, kv[t * 32 + lane] >> 24);
            __syncwarp();
            unsigned int b3 = warp_sel(hh, rem);
            ((uint4*)hh)[lane]      = make_uint4(0u, 0u, 0u, 0u);
            ((uint4*)hh)[lane + 32] = make_uint4(0u, 0u, 0u, 0u);
            __syncwarp();
            for (int t = 0; t < 50; t++) {
                unsigned int key = kv[t * 32 + lane];
                if ((key >> 24) == b3) atomicAdd(&hh[(key >> 16) & 0xFFu], 1u);
            }
            __syncwarp();
            unsigned int b2 = warp_sel(hh, rem);
            pref16 = (b3 << 8) | b2;
        }
        int cnt = 0;
        float sum_hi = 0.f;
        for (int t = 0; t < 13; t++) {
            int idx = t * 32 + lane;
            bool ok = idx < 400;
            uint4 kk = ok ? ((const uint4*)kv)[idx] : make_uint4(0u, 0u, 0u, 0u);
            #define CPROC(KEY)                                                      \
            {                                                                       \
                unsigned int hi = (KEY) >> 16;                                      \
                bool isc = ok && (hi == pref16);                                    \
                if (ok && hi > pref16) sum_hi += key2f(KEY);                        \
                unsigned int bal = __ballot_sync(0xffffffffu, isc);                 \
                if (isc) {                                                          \
                    int pos = cnt + __popc(bal & lmask);                            \
                    if (pos < 256) cd[pos] = (KEY);                                 \
                }                                                                   \
                cnt += __popc(bal);                                                 \
            }
            CPROC(kk.x) CPROC(kk.y) CPROC(kk.z) CPROC(kk.w)
            #undef CPROC
        }
        __syncwarp();
        unsigned int pref;
        float Spart;
        if (cnt <= 256) {
            int iters = (cnt + 31) >> 5;
            ((uint4*)hh)[lane]      = make_uint4(0u, 0u, 0u, 0u);
            ((uint4*)hh)[lane + 32] = make_uint4(0u, 0u, 0u, 0u);
            __syncwarp();
            for (int t = 0; t < iters; t++) {
                int idx = t * 32 + lane;
                if (idx < cnt) atomicAdd(&hh[(cd[idx] >> 8) & 0xFFu], 1u);
            }
            __syncwarp();
            unsigned int b1 = warp_sel(hh, rem);
            ((uint4*)hh)[lane]      = make_uint4(0u, 0u, 0u, 0u);
            ((uint4*)hh)[lane + 32] = make_uint4(0u, 0u, 0u, 0u);
            __syncwarp();
            for (int t = 0; t < iters; t++) {
                int idx = t * 32 + lane;
                if (idx < cnt) {
                    unsigned int key = cd[idx];
                    if (((key >> 8) & 0xFFu) == b1) atomicAdd(&hh[key & 0xFFu], 1u);
                }
            }
            __syncwarp();
            unsigned int b0 = warp_sel(hh, rem);
            pref = (pref16 << 16) | (b1 << 8) | b0;
            float Sc = 0.f;
            for (int t = 0; t < iters; t++) {
                int idx = t * 32 + lane;
                if (idx < cnt) {
                    unsigned int key = cd[idx];
                    if (key >= pref) Sc += key2f(key);
                }
            }
            Spart = sum_hi + Sc;
        } else {
            ((uint4*)hh)[lane]      = make_uint4(0u, 0u, 0u, 0u);
            ((uint4*)hh)[lane + 32] = make_uint4(0u, 0u, 0u, 0u);
            __syncwarp();
            for (int t = 0; t < 50; t++) {
                unsigned int key = kv[t * 32 + lane];
                if ((key >> 16) == pref16) atomicAdd(&hh[(key >> 8) & 0xFFu], 1u);
            }
            __syncwarp();
            unsigned int b1 = warp_sel(hh, rem);
            unsigned int pref24 = (pref16 << 8) | b1;
            ((uint4*)hh)[lane]      = make_uint4(0u, 0u, 0u, 0u);
            ((uint4*)hh)[lane + 32] = make_uint4(0u, 0u, 0u, 0u);
            __syncwarp();
            for (int t = 0; t < 50; t++) {
                unsigned int key = kv[t * 32 + lane];
                if ((key >> 8) == pref24) atomicAdd(&hh[key & 0xFFu], 1u);
            }
            __syncwarp();
            unsigned int b0 = warp_sel(hh, rem);
            pref = (pref24 << 8) | b0;
            float Sf = 0.f;
            for (int t = 0; t < 50; t++) {
                unsigned int key = kv[t * 32 + lane];
                if (key >= pref) Sf += key2f(key);
            }
            Spart = Sf;
        }
        #pragma unroll
        for (int o = 16; o; o >>= 1) Spart += __shfl_xor_sync(0xffffffffu, Spart, o);
        if (lane == 0) {
            thf[r] = key2f(pref);
            ivs[r] = 1.f / Spart;
        }
    }
    __syncthreads();

    // ---- phase 2: out = P @ V^T via TF32 MMA (P hi-only, V hi+lo), K split ----
    const float* V = g_qkv1 + (b * C3 + 512 + h * HD) * NN;
    unsigned int* psu = (unsigned int*)ps;
    unsigned int* vsu = (unsigned int*)vs;
    int g = lane >> 2, c = lane & 3;
    int kg = w >> 2;
    int mt = w & 3;
    float acc[4][4] = {};
    for (int j0 = 0; j0 < NN; j0 += 64) {
        __syncthreads();
        #pragma unroll
        for (int l = 0; l < 4; l++) {
            int f = tid + 256 * l;
            int rr = f >> 4, c4 = f & 15;
            float4 e4 = *(const float4*)&A[(size_t)(row0 + rr) * NN + j0 + c4 * 4];
            float th = thf[rr], ivv = ivs[rr];
            float p0 = (e4.x >= th) ? e4.x * ivv : 0.f;
            float p1 = (e4.y >= th) ? e4.y * ivv : 0.f;
            float p2 = (e4.z >= th) ? e4.z * ivv : 0.f;
            float p3 = (e4.w >= th) ? e4.w * ivv : 0.f;
            psu[rr * PPAD + c4 * 4 + 0] = f2tf32(p0);
            psu[rr * PPAD + c4 * 4 + 1] = f2tf32(p1);
            psu[rr * PPAD + c4 * 4 + 2] = f2tf32(p2);
            psu[rr * PPAD + c4 * 4 + 3] = f2tf32(p3);
        }
        #pragma unroll
        for (int l = 0; l < 2; l++) {
            int f = tid + 256 * l;
            int d = f >> 4, j4 = f & 15;
            float4 vv = *(const float4*)&V[d * NN + j0 + j4 * 4];
            unsigned int h0 = f2tf32(vv.x), h1 = f2tf32(vv.y);
            unsigned int h2 = f2tf32(vv.z), h3 = f2tf32(vv.w);
            vsu[d * PPAD + j4 * 4 + 0] = h0;
            vsu[d * PPAD + j4 * 4 + 1] = h1;
            vsu[d * PPAD + j4 * 4 + 2] = h2;
            vsu[d * PPAD + j4 * 4 + 3] = h3;
            vsu[d * PPAD + 68 + j4 * 4 + 0] = f2tf32(vv.x - __uint_as_float(h0));
            vsu[d * PPAD + 68 + j4 * 4 + 1] = f2tf32(vv.y - __uint_as_float(h1));
            vsu[d * PPAD + 68 + j4 * 4 + 2] = f2tf32(vv.z - __uint_as_float(h2));
            vsu[d * PPAD + 68 + j4 * 4 + 3] = f2tf32(vv.w - __uint_as_float(h3));
        }
        __syncthreads();
        #pragma unroll
        for (int ks = 0; ks < 4; ks++) {
            int k = kg * 32 + ks * 8;
            int rb = mt * 16;
            unsigned int ah[4];
            ah[0] = psu[(rb + g) * PPAD + k + c];
            ah[1] = psu[(rb + 8 + g) * PPAD + k + c];
            ah[2] = psu[(rb + g) * PPAD + k + c + 4];
            ah[3] = psu[(rb + 8 + g) * PPAD + k + c + 4];
            #pragma unroll
            for (int nt = 0; nt < 4; nt++) {
                int n0 = nt * 8 + g;
                unsigned int b0h = vsu[n0 * PPAD + k + c];
                unsigned int b1h = vsu[n0 * PPAD + k + c + 4];
                unsigned int b0l = vsu[n0 * PPAD + 68 + k + c];
                unsigned int b1l = vsu[n0 * PPAD + 68 + k + c + 4];
                mma_tf32(acc[nt], ah, b0h, b1h);
                mma_tf32(acc[nt], ah, b0l, b1l);
            }
        }
    }
    __syncthreads();
    if (kg == 1) {
        #pragma unroll
        for (int nt = 0; nt < 4; nt++)
            #pragma unroll
            for (int v = 0; v < 2; v++) {
                int r = mt * 16 + v * 8 + g;
                *(float2*)&red[r * 34 + nt * 8 + 2 * c] =
                    make_float2(acc[nt][2 * v], acc[nt][2 * v + 1]);
            }
    }
    __syncthreads();
    if (kg == 0) {
        #pragma unroll
        for (int nt = 0; nt < 4; nt++)
            #pragma unroll
            for (int v = 0; v < 2; v++) {
                int r = mt * 16 + v * 8 + g;
                float2 o = *(float2*)&red[r * 34 + nt * 8 + 2 * c];
                o.x += acc[nt][2 * v];
                o.y += acc[nt][2 * v + 1];
                *(float2*)&g_attout[(size_t)(b * NN + row0 + r) * CC + h * HD + nt * 8 + 2 * c] = o;
            }
    }
}

// ---------------- K7: output projection ----------------
__global__ void k_proj(const float* __restrict__ w, const float* __restrict__ bias,
                       float* __restrict__ out) {
    __shared__ float ws[32][65];
    __shared__ float as[32][65];
    int b = blockIdx.z;
    int co0 = blockIdx.y * 64, p0 = blockIdx.x * 64;
    int tid = threadIdx.x, tx = tid & 15, ty = tid >> 4;
    float acc[4][4] = {};
    for (int k0 = 0; k0 < 256; k0 += 32) {
        #pragma unroll
        for (int l = 0; l < 8; l++) {
            int idx = tid + 256 * l;
            int r = idx >> 5, c = idx & 31;
            ws[c][r] = w[(co0 + r) * 256 + k0 + c];
        }
        #pragma unroll
        for (int l = 0; l < 8; l++) {
            int idx = tid + 256 * l;
            int p = idx >> 5, c = idx & 31;
            as[c][p] = g_attout[(size_t)(b * NN + p0 + p) * CC + k0 + c];
        }
        __syncthreads();
        #pragma unroll
        for (int kk = 0; kk < 32; kk++) {
            float a[4], bv[4];
            #pragma unroll
            for (int i = 0; i < 4; i++) a[i] = ws[kk][ty * 4 + i];
            #pragma unroll
            for (int j = 0; j < 4; j++) bv[j] = as[kk][tx * 4 + j];
            #pragma unroll
            for (int i = 0; i < 4; i++)
                #pragma unroll
                for (int j = 0; j < 4; j++) acc[i][j] += a[i] * bv[j];
        }
        __syncthreads();
    }
    #pragma unroll
    for (int i = 0; i < 4; i++) {
        int co = co0 + ty * 4 + i;
        float bv = bias[co];
        #pragma unroll
        for (int j = 0; j < 4; j++)
            out[(b * CC + co) * NN + p0 + tx * 4 + j] = acc[i][j] + bv;
    }
}

extern "C" void kernel_launch(void* const* d_in, const int* in_sizes, int n_in,
                              void* d_out, int out_size) {
    const float* x      = (const float*)d_in[0];
    const float* qkv_w  = (const float*)d_in[1];
    const float* qkv_b  = (const float*)d_in[2];
    const float* pos_w  = (const float*)d_in[3];
    const float* pos_b  = (const float*)d_in[4];
    const float* proj_w = (const float*)d_in[5];
    const float* proj_b = (const float*)d_in[6];
    const float* g1w    = (const float*)d_in[7];
    const float* g1b    = (const float*)d_in[8];
    const float* g2w    = (const float*)d_in[9];
    const float* g2b    = (const float*)d_in[10];
    float* out = (float*)d_out;

    static int configured = 0;
    if (!configured) {
        cudaFuncSetAttribute(k_qk, cudaFuncAttributeMaxDynamicSharedMemorySize, QK_SMEM);
        cudaFuncSetAttribute(k_qkv, cudaFuncAttributeMaxDynamicSharedMemorySize, QK_SMEM);
        cudaFuncSetAttribute(k_spv, cudaFuncAttributeMaxDynamicSharedMemorySize, SPV_SMEM);
        configured = 1;
    }

    k_zero<<<(BH * NN + 255) / 256, 256>>>();
    k_qkv<<<dim3(13, 6, 2), 256, QK_SMEM>>>(x, qkv_w, qkv_b);
    k_dw<<<BB * C3, 256>>>(pos_w, pos_b);
    k_qk<<<dim3(13, 13, 16), 256, QK_SMEM>>>();
    k_gate<<<BH, 256>>>(g1w, g1b, g2w, g2b);
    k_spv<<<dim3(25, 16), 256, SPV_SMEM>>>();
    k_proj<<<dim3(25, 4, 2), 256>>>(proj_w, proj_b, out);
}

// round 16
// speedup vs baseline: 1.0300x; 1.0216x over previous
#include <cuda_runtime.h>
#include <math.h>

#define BB 2
#define CC 256
#define NHEADS 8
#define HD 32
#define NN 1600
#define C3 768
#define BH 16
#define SCALE 0.17677669529663687f  // 1/sqrt(32)
#define QPAD 73

// ---------------- scratch ----------------
__device__ float g_qkv0[BB * C3 * NN];
__device__ float g_qkv1[BB * C3 * NN];
__device__ float g_attn[(size_t)BH * NN * NN];     // e = exp(logit), all > 0
__device__ float g_S[BH * NN];
__device__ float g_T[BH * NN];
__device__ int   g_keep[BH];
__device__ float g_attout[BB * NN * CC];

// ---------------- helpers ----------------
__device__ __forceinline__ float key2f(unsigned int k) {
    return __uint_as_float(k ^ 0x80000000u);
}

__device__ __forceinline__ unsigned int f2tf32(float x) {
    unsigned int r;
    asm("cvt.rna.tf32.f32 %0, %1;" : "=r"(r) : "f"(x));
    return r;
}

__device__ __forceinline__ void mma_tf32(float* cc, const unsigned int* a,
                                         unsigned int b0, unsigned int b1) {
    asm volatile(
        "mma.sync.aligned.m16n8k8.row.col.f32.tf32.tf32.f32 "
        "{%0,%1,%2,%3}, {%4,%5,%6,%7}, {%8,%9}, {%0,%1,%2,%3};"
        : "+f"(cc[0]), "+f"(cc[1]), "+f"(cc[2]), "+f"(cc[3])
        : "r"(a[0]), "r"(a[1]), "r"(a[2]), "r"(a[3]), "r"(b0), "r"(b1));
}

__device__ __forceinline__ float bsum(float v, volatile float* sh) {
    #pragma unroll
    for (int o = 16; o; o >>= 1) v += __shfl_xor_sync(0xffffffffu, v, o);
    if ((threadIdx.x & 31) == 0) sh[threadIdx.x >> 5] = v;
    __syncthreads();
    if (threadIdx.x == 0) {
        float r = 0.f;
        #pragma unroll
        for (int i = 0; i < 8; i++) r += sh[i];
        sh[0] = r;
    }
    __syncthreads();
    float r = sh[0];
    __syncthreads();
    return r;
}

// match-aggregated add: for clustered bytes only
__device__ __forceinline__ void hadd(unsigned int* hh, unsigned int byte_or_dummy) {
    unsigned int peers = __match_any_sync(0xffffffffu, byte_or_dummy);
    int lane = threadIdx.x & 31;
    if (byte_or_dummy <= 255u && lane == (__ffs(peers) - 1))
        atomicAdd(&hh[byte_or_dummy], (unsigned int)__popc(peers));
}

__device__ __forceinline__ unsigned int warp_sel(const unsigned int* hh, int& rem) {
    int lane = threadIdx.x & 31;
    unsigned int bins[8], loc[8];
    #pragma unroll
    for (int k = 0; k < 8; k++) bins[k] = hh[lane * 8 + k];
    loc[7] = bins[7];
    #pragma unroll
    for (int k = 6; k >= 0; k--) loc[k] = loc[k + 1] + bins[k];
    unsigned int lsum = loc[0];
    unsigned int v = lsum;
    #pragma unroll
    for (int off = 1; off < 32; off <<= 1) {
        unsigned int o = __shfl_down_sync(0xffffffffu, v, off);
        if (lane + off < 32) v += o;
    }
    unsigned int above = v - lsum;
    int foundk = -1;
    int newrem = 0;
    #pragma unroll
    for (int k = 0; k < 8; k++) {
        unsigned int cum = loc[k] + above;
        unsigned int cumn = ((k < 7) ? loc[k + 1] : 0u) + above;
        if (cum >= (unsigned int)rem && cumn < (unsigned int)rem) {
            foundk = k;
            newrem = rem - (int)cumn;
        }
    }
    unsigned int ball = __ballot_sync(0xffffffffu, foundk >= 0);
    int src = __ffs(ball) - 1;
    unsigned int b = (unsigned int)__shfl_sync(0xffffffffu, lane * 8 + foundk, src);
    rem = __shfl_sync(0xffffffffu, newrem, src);
    return b;
}

// ---------------- K0 ----------------
__global__ void k_zero() {
    int i = blockIdx.x * 256 + threadIdx.x;
    if (i < BH * NN) { g_S[i] = 0.f; g_T[i] = 0.f; }
}

// ---------------- K1: QKV 1x1 conv via 2-term TF32 MMA (W hi-only, X hi+lo) ----------------
__global__ __launch_bounds__(256, 2) void k_qkv(const float* __restrict__ x,
                                                const float* __restrict__ w,
                                                const float* __restrict__ bias) {
    extern __shared__ float dsm[];
    float* ws2 = dsm;
    float* xs2 = dsm + 128 * QPAD;
    unsigned int* wrow = (unsigned int*)ws2;
    unsigned int* xrow = (unsigned int*)xs2;
    int b = blockIdx.z;
    int oc0 = blockIdx.y * 128, p0 = blockIdx.x * 128;
    int tid = threadIdx.x, wid = tid >> 5, lane = tid & 31;
    int g = lane >> 2, c = lane & 3;
    int R0 = (wid & 3) * 32, C0 = (wid >> 2) * 64;

    float acc[2][8][4] = {};
    for (int k0 = 0; k0 < 256; k0 += 32) {
        __syncthreads();
        #pragma unroll
        for (int l = 0; l < 4; l++) {
            int f = tid + 256 * l;
            int oc = f >> 3, k4 = f & 7;
            float4 v = *(const float4*)&w[(oc0 + oc) * 256 + k0 + k4 * 4];
            wrow[oc * QPAD + k4 * 4 + 0] = f2tf32(v.x);
            wrow[oc * QPAD + k4 * 4 + 1] = f2tf32(v.y);
            wrow[oc * QPAD + k4 * 4 + 2] = f2tf32(v.z);
            wrow[oc * QPAD + k4 * 4 + 3] = f2tf32(v.w);
        }
        #pragma unroll
        for (int l = 0; l < 4; l++) {
            int f = tid + 256 * l;
            int d = f >> 5, i4 = f & 31;
            int i = i4 * 4;
            int gp = p0 + i;
            float4 v = (gp < NN) ? *(const float4*)&x[(b * 256 + k0 + d) * NN + gp]
                                 : make_float4(0.f, 0.f, 0.f, 0.f);
            #pragma unroll
            for (int e = 0; e < 4; e++) {
                float xv = (&v.x)[e];
                unsigned int hi = f2tf32(xv);
                xrow[(i + e) * QPAD + d]      = hi;
                xrow[(i + e) * QPAD + 36 + d] = f2tf32(xv - __uint_as_float(hi));
            }
        }
        __syncthreads();
        #pragma unroll
        for (int ks = 0; ks < 4; ks++) {
            int kk = ks * 8;
            unsigned int ah[2][4];
            #pragma unroll
            for (int mt = 0; mt < 2; mt++) {
                int rb = R0 + mt * 16;
                ah[mt][0] = wrow[(rb + g) * QPAD + kk + c];
                ah[mt][1] = wrow[(rb + 8 + g) * QPAD + kk + c];
                ah[mt][2] = wrow[(rb + g) * QPAD + kk + c + 4];
                ah[mt][3] = wrow[(rb + 8 + g) * QPAD + kk + c + 4];
            }
            #pragma unroll
            for (int p = 0; p < 2; p++) {
                int boff = p * 36;
                #pragma unroll
                for (int nt = 0; nt < 8; nt++) {
                    int n0 = C0 + nt * 8 + g;
                    unsigned int b0 = xrow[n0 * QPAD + boff + kk + c];
                    unsigned int b1 = xrow[n0 * QPAD + boff + kk + c + 4];
                    mma_tf32(acc[0][nt], ah[0], b0, b1);
                    mma_tf32(acc[1][nt], ah[1], b0, b1);
                }
            }
        }
    }
    #pragma unroll
    for (int mt = 0; mt < 2; mt++) {
        #pragma unroll
        for (int v = 0; v < 2; v++) {
            int row = oc0 + R0 + mt * 16 + v * 8 + g;
            float bv = bias[row];
            #pragma unroll
            for (int nt = 0; nt < 8; nt++) {
                int col = p0 + C0 + nt * 8 + 2 * c;
                if (col < NN)
                    *(float2*)&g_qkv0[(b * C3 + row) * NN + col] =
                        make_float2(acc[mt][nt][2 * v] + bv, acc[mt][nt][2 * v + 1] + bv);
            }
        }
    }
}
#define QK_SMEM (2 * 128 * QPAD * 4)

// ---------------- K2: depthwise 3x3, smem-tiled per (b,channel) ----------------
__global__ __launch_bounds__(256) void k_dw(const float* __restrict__ pw,
                                            const float* __restrict__ pb) {
    __shared__ float img[NN];
    int bc = blockIdx.x;
    int ch = bc % C3;
    const float* src = g_qkv0 + (size_t)bc * NN;
    int tid = threadIdx.x;
    #pragma unroll
    for (int l = 0; l < 2; l++) {
        int i = tid + 256 * l;
        if (i < 400) ((float4*)img)[i] = ((const float4*)src)[i];
    }
    __syncthreads();
    float w0 = pw[ch * 9 + 0], w1 = pw[ch * 9 + 1], w2 = pw[ch * 9 + 2];
    float w3 = pw[ch * 9 + 3], w4 = pw[ch * 9 + 4], w5 = pw[ch * 9 + 5];
    float w6 = pw[ch * 9 + 6], w7 = pw[ch * 9 + 7], w8 = pw[ch * 9 + 8];
    float bv = pb[ch];
    float* dst = g_qkv1 + (size_t)bc * NN;
    #pragma unroll
    for (int l = 0; l < 7; l++) {
        int i = tid + 256 * l;
        if (i >= NN) break;
        int y = i / 40, x = i - y * 40;
        bool yn = y > 0, ys = y < 39, xw = x > 0, xe = x < 39;
        float s = bv + w4 * img[i];
        if (yn) {
            if (xw) s += w0 * img[i - 41];
            s += w1 * img[i - 40];
            if (xe) s += w2 * img[i - 39];
        }
        if (xw) s += w3 * img[i - 1];
        if (xe) s += w5 * img[i + 1];
        if (ys) {
            if (xw) s += w6 * img[i + 39];
            s += w7 * img[i + 40];
            if (xe) s += w8 * img[i + 41];
        }
        dst[i] = s;
    }
}

// ---------------- K3: e = exp(scale*QK^T) via 2-term TF32 (Q hi-only, K hi+lo) ----------------
__global__ __launch_bounds__(256, 2) void k_qk() {
    extern __shared__ float dsm[];
    float* qs2 = dsm;
    float* ks2 = dsm + 128 * QPAD;
    int bh = blockIdx.z;
    int b = bh >> 3, h = bh & 7;
    int i0 = blockIdx.y * 128, j0 = blockIdx.x * 128;
    int tid = threadIdx.x, wid = tid >> 5, lane = tid & 31;
    int g = lane >> 2, c = lane & 3;
    int R0 = (wid & 3) * 32, C0 = (wid >> 2) * 64;
    const float* qp = g_qkv1 + (b * C3 + h * HD) * NN;
    const float* kp = g_qkv1 + (b * C3 + 256 + h * HD) * NN;

    #pragma unroll
    for (int l = 0; l < 4; l++) {
        int f = tid + 256 * l;
        int d = f >> 5, i4 = f & 31;
        int i = i4 * 4;
        int gi = i0 + i, gj = j0 + i;
        float4 vq = (gi < NN) ? *(const float4*)&qp[d * NN + gi] : make_float4(0.f, 0.f, 0.f, 0.f);
        float4 vk = (gj < NN) ? *(const float4*)&kp[d * NN + gj] : make_float4(0.f, 0.f, 0.f, 0.f);
        #pragma unroll
        for (int e = 0; e < 4; e++) {
            ((unsigned int*)qs2)[(i + e) * QPAD + d] = f2tf32((&vq.x)[e]);
            float xk = (&vk.x)[e];
            unsigned int kh = f2tf32(xk);
            ((unsigned int*)ks2)[(i + e) * QPAD + d]      = kh;
            ((unsigned int*)ks2)[(i + e) * QPAD + 36 + d] = f2tf32(xk - __uint_as_float(kh));
        }
    }
    __syncthreads();

    const unsigned int* qrow = (const unsigned int*)qs2;
    const unsigned int* krow = (const unsigned int*)ks2;
    float acc[2][8][4] = {};
    #pragma unroll
    for (int ks = 0; ks < 4; ks++) {
        int k0 = ks * 8;
        unsigned int ah[2][4];
        #pragma unroll
        for (int mt = 0; mt < 2; mt++) {
            int rb = R0 + mt * 16;
            ah[mt][0] = qrow[(rb + g) * QPAD + k0 + c];
            ah[mt][1] = qrow[(rb + 8 + g) * QPAD + k0 + c];
            ah[mt][2] = qrow[(rb + g) * QPAD + k0 + c + 4];
            ah[mt][3] = qrow[(rb + 8 + g) * QPAD + k0 + c + 4];
        }
        #pragma unroll
        for (int p = 0; p < 2; p++) {
            int boff = p * 36;
            #pragma unroll
            for (int nt = 0; nt < 8; nt++) {
                int n0 = C0 + nt * 8 + g;
                unsigned int b0 = krow[n0 * QPAD + boff + k0 + c];
                unsigned int b1 = krow[n0 * QPAD + boff + k0 + c + 4];
                mma_tf32(acc[0][nt], ah[0], b0, b1);
                mma_tf32(acc[1][nt], ah[1], b0, b1);
            }
        }
    }

    float* outp = g_attn + (size_t)bh * NN * NN;
    #pragma unroll
    for (int mt = 0; mt < 2; mt++) {
        #pragma unroll
        for (int v = 0; v < 2; v++) {
            int row = i0 + R0 + mt * 16 + v * 8 + g;
            bool rok = row < NN;
            float se = 0.f, te = 0.f;
            #pragma unroll
            for (int nt = 0; nt < 8; nt++) {
                int col = j0 + C0 + nt * 8 + 2 * c;
                float a0 = acc[mt][nt][2 * v] * SCALE;
                float a1 = acc[mt][nt][2 * v + 1] * SCALE;
                float e0 = __expf(a0), e1 = __expf(a1);
                if (rok && col < NN) {
                    *(float2*)&outp[(size_t)row * NN + col] = make_float2(e0, e1);
                    se += e0 + e1;
                    te += a0 * e0 + a1 * e1;
                }
            }
            se += __shfl_xor_sync(0xffffffffu, se, 1);
            te += __shfl_xor_sync(0xffffffffu, te, 1);
            se += __shfl_xor_sync(0xffffffffu, se, 2);
            te += __shfl_xor_sync(0xffffffffu, te, 2);
            if (c == 0 && rok) {
                atomicAdd(&g_S[bh * NN + row], se);
                atomicAdd(&g_T[bh * NN + row], te);
            }
        }
    }
}

// ---------------- K4: entropy gate ----------------
__global__ void k_gate(const float* __restrict__ g1w, const float* __restrict__ g1b,
                       const float* __restrict__ g2w, const float* __restrict__ g2b) {
    int bh = blockIdx.x;
    __shared__ float sh[8];
    float s = 0.f;
    for (int i = threadIdx.x; i < NN; i += 256) {
        float S = g_S[bh * NN + i];
        float T = g_T[bh * NN + i];
        s += logf(S) - T / S;
    }
    s = bsum(s, sh);
    if (threadIdx.x == 0) {
        float e = s / (float)NN;
        float z = g2b[0];
        #pragma unroll
        for (int i = 0; i < 16; i++) {
            float hid = fmaxf(e * g1w[i] + g1b[i], 0.f);
            z += hid * g2w[i];
        }
        float ratio = 1.f / (1.f + expf(-z)) * 0.9f + 0.1f;
        int keep = (int)ceilf(ratio * (float)NN);
        keep = min(max(keep, 1), NN);
        g_keep[bh] = keep;
    }
}

// ---------------- K5: fused select + PV (PV single-term TF32: P-hi x V-hi) ----------------
#define SPV_SMEM 67584
#define PPAD 132
__global__ __launch_bounds__(256) void k_spv() {
    extern __shared__ float pool[];
    unsigned int* keybuf = (unsigned int*)pool;
    unsigned int* histb  = (unsigned int*)pool + 8 * 1600;
    unsigned int* candb  = (unsigned int*)pool + 8 * 1600 + 8 * 256;
    float* ps  = pool;                           // [64][PPAD] (hi only used)
    float* vs  = pool + 64 * PPAD;               // [32][PPAD] (hi only used)
    float* red = pool + 64 * PPAD + 32 * PPAD;   // [64][34]
    __shared__ float thf[64];
    __shared__ float ivs[64];

    int bh = blockIdx.y;
    int b = bh >> 3, h = bh & 7;
    int row0 = blockIdx.x * 64;
    int tid = threadIdx.x, w = tid >> 5, lane = tid & 31;
    unsigned int lmask = (1u << lane) - 1u;
    const float* A = g_attn + (size_t)bh * NN * NN;
    int keep = g_keep[bh];

    unsigned int* kv = keybuf + w * 1600;
    unsigned int* hh = histb + w * 256;
    unsigned int* cd = candb + w * 256;

    // ---- phase 1: warp-per-row select ----
    for (int i = 0; i < 8; i++) {
        int r = w * 8 + i;
        const uint4* src = (const uint4*)(A + (size_t)(row0 + r) * NN);
        ((uint4*)hh)[lane]      = make_uint4(0u, 0u, 0u, 0u);
        ((uint4*)hh)[lane + 32] = make_uint4(0u, 0u, 0u, 0u);
        __syncwarp();
        float Sall = 0.f;
        unsigned int andb = 0xFFu, orb = 0u;
        for (int t = 0; t < 13; t++) {
            int idx = t * 32 + lane;
            bool ok = idx < 400;
            if (ok) {
                uint4 kk = src[idx];
                kk.x |= 0x80000000u; kk.y |= 0x80000000u;
                kk.z |= 0x80000000u; kk.w |= 0x80000000u;
                ((uint4*)kv)[idx] = kk;
                Sall += key2f(kk.x) + key2f(kk.y) + key2f(kk.z) + key2f(kk.w);
                andb &= (kk.x >> 24) & (kk.y >> 24) & (kk.z >> 24) & (kk.w >> 24);
                orb  |= (kk.x >> 24) | (kk.y >> 24) | (kk.z >> 24) | (kk.w >> 24);
            }
        }
        #pragma unroll
        for (int o = 16; o; o >>= 1) {
            Sall += __shfl_xor_sync(0xffffffffu, Sall, o);
            andb &= __shfl_xor_sync(0xffffffffu, andb, o);
            orb  |= __shfl_xor_sync(0xffffffffu, orb, o);
        }
        if (keep == NN) {
            if (lane == 0) { thf[r] = 0.f; ivs[r] = 1.f / Sall; }
            continue;
        }
        __syncwarp();
        int rem = keep;
        unsigned int pref16;
        if (andb == orb) {
            for (int t = 0; t < 13; t++) {
                int idx = t * 32 + lane;
                if (idx < 400) {
                    uint4 kk = ((const uint4*)kv)[idx];
                    atomicAdd(&hh[(kk.x >> 16) & 0xFFu], 1u);
                    atomicAdd(&hh[(kk.y >> 16) & 0xFFu], 1u);
                    atomicAdd(&hh[(kk.z >> 16) & 0xFFu], 1u);
                    atomicAdd(&hh[(kk.w >> 16) & 0xFFu], 1u);
                }
            }
            __syncwarp();
            unsigned int b2 = warp_sel(hh, rem);
            pref16 = (andb << 8) | b2;
        } else {
            for (int t = 0; t < 50; t++)
                hadd(hh, kv[t * 32 + lane] >> 24);
            __syncwarp();
            unsigned int b3 = warp_sel(hh, rem);
            ((uint4*)hh)[lane]      = make_uint4(0u, 0u, 0u, 0u);
            ((uint4*)hh)[lane + 32] = make_uint4(0u, 0u, 0u, 0u);
            __syncwarp();
            for (int t = 0; t < 50; t++) {
                unsigned int key = kv[t * 32 + lane];
                if ((key >> 24) == b3) atomicAdd(&hh[(key >> 16) & 0xFFu], 1u);
            }
            __syncwarp();
            unsigned int b2 = warp_sel(hh, rem);
            pref16 = (b3 << 8) | b2;
        }
        int cnt = 0;
        float sum_hi = 0.f;
        for (int t = 0; t < 13; t++) {
            int idx = t * 32 + lane;
            bool ok = idx < 400;
            uint4 kk = ok ? ((const uint4*)kv)[idx] : make_uint4(0u, 0u, 0u, 0u);
            #define CPROC(KEY)                                                      \
            {                                                                       \
                unsigned int hi = (KEY) >> 16;                                      \
                bool isc = ok && (hi == pref16);                                    \
                if (ok && hi > pref16) sum_hi += key2f(KEY);                        \
                unsigned int bal = __ballot_sync(0xffffffffu, isc);                 \
                if (isc) {                                                          \
                    int pos = cnt + __popc(bal & lmask);                            \
                    if (pos < 256) cd[pos] = (KEY);                                 \
                }                                                                   \
                cnt += __popc(bal);                                                 \
            }
            CPROC(kk.x) CPROC(kk.y) CPROC(kk.z) CPROC(kk.w)
            #undef CPROC
        }
        __syncwarp();
        unsigned int pref;
        float Spart;
        if (cnt <= 256) {
            int iters = (cnt + 31) >> 5;
            ((uint4*)hh)[lane]      = make_uint4(0u, 0u, 0u, 0u);
            ((uint4*)hh)[lane + 32] = make_uint4(0u, 0u, 0u, 0u);
            __syncwarp();
            for (int t = 0; t < iters; t++) {
                int idx = t * 32 + lane;
                if (idx < cnt) atomicAdd(&hh[(cd[idx] >> 8) & 0xFFu], 1u);
            }
            __syncwarp();
            unsigned int b1 = warp_sel(hh, rem);
            ((uint4*)hh)[lane]      = make_uint4(0u, 0u, 0u, 0u);
            ((uint4*)hh)[lane + 32] = make_uint4(0u, 0u, 0u, 0u);
            __syncwarp();
            for (int t = 0; t < iters; t++) {
                int idx = t * 32 + lane;
                if (idx < cnt) {
                    unsigned int key = cd[idx];
                    if (((key >> 8) & 0xFFu) == b1) atomicAdd(&hh[key & 0xFFu], 1u);
                }
            }
            __syncwarp();
            unsigned int b0 = warp_sel(hh, rem);
            pref = (pref16 << 16) | (b1 << 8) | b0;
            float Sc = 0.f;
            for (int t = 0; t < iters; t++) {
                int idx = t * 32 + lane;
                if (idx < cnt) {
                    unsigned int key = cd[idx];
                    if (key >= pref) Sc += key2f(key);
                }
            }
            Spart = sum_hi + Sc;
        } else {
            ((uint4*)hh)[lane]      = make_uint4(0u, 0u, 0u, 0u);
            ((uint4*)hh)[lane + 32] = make_uint4(0u, 0u, 0u, 0u);
            __syncwarp();
            for (int t = 0; t < 50; t++) {
                unsigned int key = kv[t * 32 + lane];
                if ((key >> 16) == pref16) atomicAdd(&hh[(key >> 8) & 0xFFu], 1u);
            }
            __syncwarp();
            unsigned int b1 = warp_sel(hh, rem);
            unsigned int pref24 = (pref16 << 8) | b1;
            ((uint4*)hh)[lane]      = make_uint4(0u, 0u, 0u, 0u);
            ((uint4*)hh)[lane + 32] = make_uint4(0u, 0u, 0u, 0u);
            __syncwarp();
            for (int t = 0; t < 50; t++) {
                unsigned int key = kv[t * 32 + lane];
                if ((key >> 8) == pref24) atomicAdd(&hh[key & 0xFFu], 1u);
            }
            __syncwarp();
            unsigned int b0 = warp_sel(hh, rem);
            pref = (pref24 << 8) | b0;
            float Sf = 0.f;
            for (int t = 0; t < 50; t++) {
                unsigned int key = kv[t * 32 + lane];
                if (key >= pref) Sf += key2f(key);
            }
            Spart = Sf;
        }
        #pragma unroll
        for (int o = 16; o; o >>= 1) Spart += __shfl_xor_sync(0xffffffffu, Spart, o);
        if (lane == 0) {
            thf[r] = key2f(pref);
            ivs[r] = 1.f / Spart;
        }
    }
    __syncthreads();

    // ---- phase 2: out = P @ V^T via single-term TF32 MMA (hi x hi), K split ----
    const float* V = g_qkv1 + (b * C3 + 512 + h * HD) * NN;
    unsigned int* psu = (unsigned int*)ps;
    unsigned int* vsu = (unsigned int*)vs;
    int g = lane >> 2, c = lane & 3;
    int kg = w >> 2;
    int mt = w & 3;
    float acc[4][4] = {};
    for (int j0 = 0; j0 < NN; j0 += 64) {
        __syncthreads();
        #pragma unroll
        for (int l = 0; l < 4; l++) {
            int f = tid + 256 * l;
            int rr = f >> 4, c4 = f & 15;
            float4 e4 = *(const float4*)&A[(size_t)(row0 + rr) * NN + j0 + c4 * 4];
            float th = thf[rr], ivv = ivs[rr];
            float p0 = (e4.x >= th) ? e4.x * ivv : 0.f;
            float p1 = (e4.y >= th) ? e4.y * ivv : 0.f;
            float p2 = (e4.z >= th) ? e4.z * ivv : 0.f;
            float p3 = (e4.w >= th) ? e4.w * ivv : 0.f;
            psu[rr * PPAD + c4 * 4 + 0] = f2tf32(p0);
            psu[rr * PPAD + c4 * 4 + 1] = f2tf32(p1);
            psu[rr * PPAD + c4 * 4 + 2] = f2tf32(p2);
            psu[rr * PPAD + c4 * 4 + 3] = f2tf32(p3);
        }
        #pragma unroll
        for (int l = 0; l < 2; l++) {
            int f = tid + 256 * l;
            int d = f >> 4, j4 = f & 15;
            float4 vv = *(const float4*)&V[d * NN + j0 + j4 * 4];
            vsu[d * PPAD + j4 * 4 + 0] = f2tf32(vv.x);
            vsu[d * PPAD + j4 * 4 + 1] = f2tf32(vv.y);
            vsu[d * PPAD + j4 * 4 + 2] = f2tf32(vv.z);
            vsu[d * PPAD + j4 * 4 + 3] = f2tf32(vv.w);
        }
        __syncthreads();
        #pragma unroll
        for (int ks = 0; ks < 4; ks++) {
            int k = kg * 32 + ks * 8;
            int rb = mt * 16;
            unsigned int ah[4];
            ah[0] = psu[(rb + g) * PPAD + k + c];
            ah[1] = psu[(rb + 8 + g) * PPAD + k + c];
            ah[2] = psu[(rb + g) * PPAD + k + c + 4];
            ah[3] = psu[(rb + 8 + g) * PPAD + k + c + 4];
            #pragma unroll
            for (int nt = 0; nt < 4; nt++) {
                int n0 = nt * 8 + g;
                unsigned int b0h = vsu[n0 * PPAD + k + c];
                unsigned int b1h = vsu[n0 * PPAD + k + c + 4];
                mma_tf32(acc[nt], ah, b0h, b1h);
            }
        }
    }
    __syncthreads();
    if (kg == 1) {
        #pragma unroll
        for (int nt = 0; nt < 4; nt++)
            #pragma unroll
            for (int v = 0; v < 2; v++) {
                int r = mt * 16 + v * 8 + g;
                *(float2*)&red[r * 34 + nt * 8 + 2 * c] =
                    make_float2(acc[nt][2 * v], acc[nt][2 * v + 1]);
            }
    }
    __syncthreads();
    if (kg == 0) {
        #pragma unroll
        for (int nt = 0; nt < 4; nt++)
            #pragma unroll
            for (int v = 0; v < 2; v++) {
                int r = mt * 16 + v * 8 + g;
                float2 o = *(float2*)&red[r * 34 + nt * 8 + 2 * c];
                o.x += acc[nt][2 * v];
                o.y += acc[nt][2 * v + 1];
                *(float2*)&g_attout[(size_t)(b * NN + row0 + r) * CC + h * HD + nt * 8 + 2 * c] = o;
            }
    }
}

// ---------------- K7: output projection ----------------
__global__ void k_proj(const float* __restrict__ w, const float* __restrict__ bias,
                       float* __restrict__ out) {
    __shared__ float ws[32][65];
    __shared__ float as[32][65];
    int b = blockIdx.z;
    int co0 = blockIdx.y * 64, p0 = blockIdx.x * 64;
    int tid = threadIdx.x, tx = tid & 15, ty = tid >> 4;
    float acc[4][4] = {};
    for (int k0 = 0; k0 < 256; k0 += 32) {
        #pragma unroll
        for (int l = 0; l < 8; l++) {
            int idx = tid + 256 * l;
            int r = idx >> 5, c = idx & 31;
            ws[c][r] = w[(co0 + r) * 256 + k0 + c];
        }
        #pragma unroll
        for (int l = 0; l < 8; l++) {
            int idx = tid + 256 * l;
            int p = idx >> 5, c = idx & 31;
            as[c][p] = g_attout[(size_t)(b * NN + p0 + p) * CC + k0 + c];
        }
        __syncthreads();
        #pragma unroll
        for (int kk = 0; kk < 32; kk++) {
            float a[4], bv[4];
            #pragma unroll
            for (int i = 0; i < 4; i++) a[i] = ws[kk][ty * 4 + i];
            #pragma unroll
            for (int j = 0; j < 4; j++) bv[j] = as[kk][tx * 4 + j];
            #pragma unroll
            for (int i = 0; i < 4; i++)
                #pragma unroll
                for (int j = 0; j < 4; j++) acc[i][j] += a[i] * bv[j];
        }
        __syncthreads();
    }
    #pragma unroll
    for (int i = 0; i < 4; i++) {
        int co = co0 + ty * 4 + i;
        float bv = bias[co];
        #pragma unroll
        for (int j = 0; j < 4; j++)
            out[(b * CC + co) * NN + p0 + tx * 4 + j] = acc[i][j] + bv;
    }
}

extern "C" void kernel_launch(void* const* d_in, const int* in_sizes, int n_in,
                              void* d_out, int out_size) {
    const float* x      = (const float*)d_in[0];
    const float* qkv_w  = (const float*)d_in[1];
    const float* qkv_b  = (const float*)d_in[2];
    const float* pos_w  = (const float*)d_in[3];
    const float* pos_b  = (const float*)d_in[4];
    const float* proj_w = (const float*)d_in[5];
    const float* proj_b = (const float*)d_in[6];
    const float* g1w    = (const float*)d_in[7];
    const float* g1b    = (const float*)d_in[8];
    const float* g2w    = (const float*)d_in[9];
    const float* g2b    = (const float*)d_in[10];
    float* out = (float*)d_out;

    static int configured = 0;
    if (!configured) {
        cudaFuncSetAttribute(k_qk, cudaFuncAttributeMaxDynamicSharedMemorySize, QK_SMEM);
        cudaFuncSetAttribute(k_qkv, cudaFuncAttributeMaxDynamicSharedMemorySize, QK_SMEM);
        cudaFuncSetAttribute(k_spv, cudaFuncAttributeMaxDynamicSharedMemorySize, SPV_SMEM);
        configured = 1;
    }

    k_zero<<<(BH * NN + 255) / 256, 256>>>();
    k_qkv<<<dim3(13, 6, 2), 256, QK_SMEM>>>(x, qkv_w, qkv_b);
    k_dw<<<BB * C3, 256>>>(pos_w, pos_b);
    k_qk<<<dim3(13, 13, 16), 256, QK_SMEM>>>();
    k_gate<<<BH, 256>>>(g1w, g1b, g2w, g2b);
    k_spv<<<dim3(25, 16), 256, SPV_SMEM>>>();
    k_proj<<<dim3(25, 4, 2), 256>>>(proj_w, proj_b, out);
}